// round 5
// baseline (speedup 1.0000x reference)
#include <cuda_runtime.h>
#include <cstddef>

#define NHAND 21
#define DMODEL 128
#define FIN 256
#define FOUT 512
#define ODIM 3
#define NTHREADS 128

typedef unsigned long long ull;

__device__ __forceinline__ ull ffma2(ull a, ull b, ull c) {
    ull d;
    asm("fma.rn.f32x2 %0, %1, %2, %3;" : "=l"(d) : "l"(a), "l"(b), "l"(c));
    return d;
}
__device__ __forceinline__ ull pack2(float lo, float hi) {
    ull d;
    asm("mov.b64 %0, {%1, %2};" : "=l"(d) : "f"(lo), "f"(hi));
    return d;
}
__device__ __forceinline__ float2 unpack2(ull v) {
    float lo, hi;
    asm("mov.b64 {%0, %1}, %2;" : "=f"(lo), "=f"(hi) : "l"(v));
    return make_float2(lo, hi);
}

struct __align__(16) Smem {
    float X[NHAND][FIN];        // layer-1 input staging (21504 B)
    float Buf[NHAND][DMODEL];   // H1, then A3@H2        (10752 B)
    float2 Apk[3][NHAND][12];   // A rows packed in m-pairs, zero padded (6048 B)
    float b1s[DMODEL];
    float b2s[DMODEL];
    float fcWs[FOUT][ODIM];     // 6144 B
    float fcbs[ODIM];
    float Out[NHAND][ODIM];
};

__global__ void __launch_bounds__(NTHREADS, 4) handnet_fused_kernel(
    const float* __restrict__ x,
    const float* __restrict__ A1, const float* __restrict__ A2, const float* __restrict__ A3,
    const float* __restrict__ W1, const float* __restrict__ b1,
    const float* __restrict__ W2, const float* __restrict__ b2,
    const float* __restrict__ W3, const float* __restrict__ b3,
    const float* __restrict__ fcW, const float* __restrict__ fcb,
    float* __restrict__ x3_out, float* __restrict__ fc_out)
{
    __shared__ Smem s;
    const int o = threadIdx.x;           // output channel 0..127
    const int b = blockIdx.x;            // batch element

    // ---------------- cooperative loads ----------------
    {
        const float4* xg = reinterpret_cast<const float4*>(x + (size_t)b * NHAND * FIN);
        float4* sx4 = reinterpret_cast<float4*>(&s.X[0][0]);
        #pragma unroll
        for (int i = 0; i < 11; i++) {
            int idx = o + i * NTHREADS;
            if (idx < NHAND * FIN / 4) sx4[idx] = xg[idx];
        }
        // A matrices packed in m-pairs (12 pairs, zero padded past m=20)
        for (int idx = o; idx < NHAND * 12; idx += NTHREADS) {
            int n = idx / 12, mm = idx % 12;
            int m0 = 2 * mm, m1 = 2 * mm + 1;
            float a1x = (m0 < NHAND) ? A1[n * NHAND + m0] : 0.f;
            float a1y = (m1 < NHAND) ? A1[n * NHAND + m1] : 0.f;
            float a2x = (m0 < NHAND) ? A2[n * NHAND + m0] : 0.f;
            float a2y = (m1 < NHAND) ? A2[n * NHAND + m1] : 0.f;
            float a3x = (m0 < NHAND) ? A3[n * NHAND + m0] : 0.f;
            float a3y = (m1 < NHAND) ? A3[n * NHAND + m1] : 0.f;
            s.Apk[0][n][mm] = make_float2(a1x, a1y);
            s.Apk[1][n][mm] = make_float2(a2x, a2y);
            s.Apk[2][n][mm] = make_float2(a3x, a3y);
        }
        s.b1s[o] = b1[o];
        s.b2s[o] = b2[o];
        for (int idx = o; idx < FOUT * ODIM; idx += NTHREADS)
            (&s.fcWs[0][0])[idx] = fcW[idx];
        if (o < ODIM) s.fcbs[o] = fcb[o];
        for (int idx = o; idx < NHAND * ODIM; idx += NTHREADS)
            (&s.Out[0][0])[idx] = 0.f;
    }
    __syncthreads();

    ull acc2[NHAND];
    float as[NHAND];
    ull P[11];

    // ---------------- layer 1: G1 = X @ W1 (K=256, k-packed) ----------------
    #pragma unroll
    for (int m = 0; m < NHAND; m++) acc2[m] = 0ull;
    for (int f0 = 0; f0 < FIN; f0 += 4) {
        const float* wr = W1 + f0 * DMODEL + o;
        float w0 = __ldg(wr);
        float w1 = __ldg(wr + DMODEL);
        float w2 = __ldg(wr + 2 * DMODEL);
        float w3 = __ldg(wr + 3 * DMODEL);
        ull wp01 = pack2(w0, w1), wp23 = pack2(w2, w3);
        #pragma unroll
        for (int m = 0; m < NHAND; m++) {
            ulonglong2 xv = *reinterpret_cast<const ulonglong2*>(&s.X[m][f0]);
            acc2[m] = ffma2(xv.x, wp01, acc2[m]);
            acc2[m] = ffma2(xv.y, wp23, acc2[m]);
        }
    }
    // horizontal add + repack for the mix
    #pragma unroll
    for (int m = 0; m < NHAND; m++) { float2 t = unpack2(acc2[m]); as[m] = t.x + t.y; }
    #pragma unroll
    for (int mm = 0; mm < 10; mm++) P[mm] = pack2(as[2 * mm], as[2 * mm + 1]);
    P[10] = pack2(as[20], 0.f);

    // A1-mix + bias + relu -> Buf (H1)
    {
        float bias = s.b1s[o];
        #pragma unroll
        for (int n = 0; n < NHAND; n++) {
            ull acc = 0ull;
            #pragma unroll
            for (int mm = 0; mm < 11; mm++) {
                float2 a = s.Apk[0][n][mm];
                acc = ffma2(pack2(a.x, a.y), P[mm], acc);
            }
            float2 t = unpack2(acc);
            s.Buf[n][o] = fmaxf(t.x + t.y + bias, 0.f);
        }
    }
    __syncthreads();

    // ---------------- layer 2: G2 = H1 @ W2 (K=128, k-packed) ----------------
    #pragma unroll
    for (int m = 0; m < NHAND; m++) acc2[m] = 0ull;
    for (int f0 = 0; f0 < DMODEL; f0 += 4) {
        const float* wr = W2 + f0 * DMODEL + o;
        float w0 = __ldg(wr);
        float w1 = __ldg(wr + DMODEL);
        float w2 = __ldg(wr + 2 * DMODEL);
        float w3 = __ldg(wr + 3 * DMODEL);
        ull wp01 = pack2(w0, w1), wp23 = pack2(w2, w3);
        #pragma unroll
        for (int m = 0; m < NHAND; m++) {
            ulonglong2 hv = *reinterpret_cast<const ulonglong2*>(&s.Buf[m][f0]);
            acc2[m] = ffma2(hv.x, wp01, acc2[m]);
            acc2[m] = ffma2(hv.y, wp23, acc2[m]);
        }
    }
    __syncthreads();   // done reading Buf before overwrite

    // A2-mix + bias + relu -> h2 (regs), then A3-mix -> Buf
    {
        #pragma unroll
        for (int m = 0; m < NHAND; m++) { float2 t = unpack2(acc2[m]); as[m] = t.x + t.y; }
        #pragma unroll
        for (int mm = 0; mm < 10; mm++) P[mm] = pack2(as[2 * mm], as[2 * mm + 1]);
        P[10] = pack2(as[20], 0.f);

        float h2[NHAND];
        float bias = s.b2s[o];
        #pragma unroll
        for (int n = 0; n < NHAND; n++) {
            ull acc = 0ull;
            #pragma unroll
            for (int mm = 0; mm < 11; mm++) {
                float2 a = s.Apk[1][n][mm];
                acc = ffma2(pack2(a.x, a.y), P[mm], acc);
            }
            float2 t = unpack2(acc);
            h2[n] = fmaxf(t.x + t.y + bias, 0.f);
        }
        #pragma unroll
        for (int mm = 0; mm < 10; mm++) P[mm] = pack2(h2[2 * mm], h2[2 * mm + 1]);
        P[10] = pack2(h2[20], 0.f);
        #pragma unroll
        for (int n = 0; n < NHAND; n++) {
            ull acc = 0ull;
            #pragma unroll
            for (int mm = 0; mm < 11; mm++) {
                float2 a = s.Apk[2][n][mm];
                acc = ffma2(pack2(a.x, a.y), P[mm], acc);
            }
            float2 t = unpack2(acc);
            s.Buf[n][o] = t.x + t.y;   // AH2 (pre-W3), no relu/bias here
        }
    }
    __syncthreads();

    // ---------------- layer 3: x3 = relu(AH2 @ W3 + b3), fused fc ----------------
    float bb3[4];
    #pragma unroll
    for (int c = 0; c < 4; c++) bb3[c] = __ldg(&b3[o + 128 * c]);

    for (int mc = 0; mc < NHAND; mc += 7) {     // 3 row chunks of 7
        ull a3c[7][4];
        #pragma unroll
        for (int mm = 0; mm < 7; mm++)
            #pragma unroll
            for (int c = 0; c < 4; c++) a3c[mm][c] = 0ull;

        for (int f0 = 0; f0 < DMODEL; f0 += 4) {
            ull wp[4][2];
            #pragma unroll
            for (int c = 0; c < 4; c++) {
                const float* wr = W3 + f0 * FOUT + o + 128 * c;
                float w0 = __ldg(wr);
                float w1 = __ldg(wr + FOUT);
                float w2 = __ldg(wr + 2 * FOUT);
                float w3 = __ldg(wr + 3 * FOUT);
                wp[c][0] = pack2(w0, w1);
                wp[c][1] = pack2(w2, w3);
            }
            #pragma unroll
            for (int mm = 0; mm < 7; mm++) {
                ulonglong2 hv = *reinterpret_cast<const ulonglong2*>(&s.Buf[mc + mm][f0]);
                #pragma unroll
                for (int c = 0; c < 4; c++) {
                    a3c[mm][c] = ffma2(hv.x, wp[c][0], a3c[mm][c]);
                    a3c[mm][c] = ffma2(hv.y, wp[c][1], a3c[mm][c]);
                }
            }
        }
        // relu + store x3 + fc partials
        #pragma unroll
        for (int mm = 0; mm < 7; mm++) {
            int m = mc + mm;
            float p0 = 0.f, p1 = 0.f, p2 = 0.f;
            #pragma unroll
            for (int c = 0; c < 4; c++) {
                float2 t = unpack2(a3c[mm][c]);
                float v = fmaxf(t.x + t.y + bb3[c], 0.f);
                int col = o + 128 * c;
                x3_out[((size_t)b * NHAND + m) * FOUT + col] = v;
                p0 = fmaf(v, s.fcWs[col][0], p0);
                p1 = fmaf(v, s.fcWs[col][1], p1);
                p2 = fmaf(v, s.fcWs[col][2], p2);
            }
            #pragma unroll
            for (int off = 16; off > 0; off >>= 1) {
                p0 += __shfl_down_sync(0xffffffffu, p0, off);
                p1 += __shfl_down_sync(0xffffffffu, p1, off);
                p2 += __shfl_down_sync(0xffffffffu, p2, off);
            }
            if ((o & 31) == 0) {
                atomicAdd(&s.Out[m][0], p0);
                atomicAdd(&s.Out[m][1], p1);
                atomicAdd(&s.Out[m][2], p2);
            }
        }
    }
    __syncthreads();

    // ---------------- write fc output ----------------
    if (o < NHAND * ODIM) {
        int n = o / ODIM, j = o % ODIM;
        fc_out[((size_t)b * NHAND + n) * ODIM + j] = s.Out[n][j] + s.fcbs[j];
    }
}

extern "C" void kernel_launch(void* const* d_in, const int* in_sizes, int n_in,
                              void* d_out, int out_size)
{
    const float* x   = (const float*)d_in[0];
    const float* A1  = (const float*)d_in[1];
    const float* A2  = (const float*)d_in[2];
    const float* A3  = (const float*)d_in[3];
    const float* W1  = (const float*)d_in[4];
    const float* b1  = (const float*)d_in[5];
    const float* W2  = (const float*)d_in[6];
    const float* b2  = (const float*)d_in[7];
    const float* W3  = (const float*)d_in[8];
    const float* b3  = (const float*)d_in[9];
    const float* fcW = (const float*)d_in[10];
    const float* fcb = (const float*)d_in[11];

    const int B = in_sizes[0] / (NHAND * FIN);
    float* x3_out = (float*)d_out;
    float* fc_out = x3_out + (size_t)B * NHAND * FOUT;

    handnet_fused_kernel<<<B, NTHREADS>>>(x, A1, A2, A3, W1, b1, W2, b2,
                                          W3, b3, fcW, fcb, x3_out, fc_out);
}

// round 6
// speedup vs baseline: 1.0002x; 1.0002x over previous
#include <cuda_runtime.h>
#include <cstddef>

#define NHAND 21
#define DMODEL 128
#define FIN 256
#define FOUT 512
#define ODIM 3
#define NTHREADS 128

typedef unsigned long long ull;

__device__ __forceinline__ ull ffma2(ull a, ull b, ull c) {
    ull d;
    asm("fma.rn.f32x2 %0, %1, %2, %3;" : "=l"(d) : "l"(a), "l"(b), "l"(c));
    return d;
}
__device__ __forceinline__ ull pack2(float lo, float hi) {
    ull d;
    asm("mov.b64 %0, {%1, %2};" : "=l"(d) : "f"(lo), "f"(hi));
    return d;
}
__device__ __forceinline__ float2 unpack2(ull v) {
    float lo, hi;
    asm("mov.b64 {%0, %1}, %2;" : "=f"(lo), "=f"(hi) : "l"(v));
    return make_float2(lo, hi);
}

struct __align__(16) Smem {
    float X[NHAND][FIN];        // layer-1 input staging (21504 B)
    float Buf[NHAND][DMODEL];   // H1, then A3@H2        (10752 B)
    float2 Apk[3][NHAND][12];   // A rows packed in m-pairs, zero padded (6048 B)
    float b1s[DMODEL];
    float b2s[DMODEL];
    float fcWs[FOUT][ODIM];     // 6144 B
    float fcbs[ODIM];
    float Out[NHAND][ODIM];
};

__global__ void __launch_bounds__(NTHREADS, 4) handnet_fused_kernel(
    const float* __restrict__ x,
    const float* __restrict__ A1, const float* __restrict__ A2, const float* __restrict__ A3,
    const float* __restrict__ W1, const float* __restrict__ b1,
    const float* __restrict__ W2, const float* __restrict__ b2,
    const float* __restrict__ W3, const float* __restrict__ b3,
    const float* __restrict__ fcW, const float* __restrict__ fcb,
    float* __restrict__ x3_out, float* __restrict__ fc_out)
{
    __shared__ Smem s;
    const int o = threadIdx.x;           // output channel 0..127
    const int b = blockIdx.x;            // batch element

    // ---------------- cooperative loads ----------------
    {
        const float4* xg = reinterpret_cast<const float4*>(x + (size_t)b * NHAND * FIN);
        float4* sx4 = reinterpret_cast<float4*>(&s.X[0][0]);
        #pragma unroll
        for (int i = 0; i < 11; i++) {
            int idx = o + i * NTHREADS;
            if (idx < NHAND * FIN / 4) sx4[idx] = xg[idx];
        }
        // A matrices packed in m-pairs (12 pairs, zero padded past m=20)
        for (int idx = o; idx < NHAND * 12; idx += NTHREADS) {
            int n = idx / 12, mm = idx % 12;
            int m0 = 2 * mm, m1 = 2 * mm + 1;
            float a1x = (m0 < NHAND) ? A1[n * NHAND + m0] : 0.f;
            float a1y = (m1 < NHAND) ? A1[n * NHAND + m1] : 0.f;
            float a2x = (m0 < NHAND) ? A2[n * NHAND + m0] : 0.f;
            float a2y = (m1 < NHAND) ? A2[n * NHAND + m1] : 0.f;
            float a3x = (m0 < NHAND) ? A3[n * NHAND + m0] : 0.f;
            float a3y = (m1 < NHAND) ? A3[n * NHAND + m1] : 0.f;
            s.Apk[0][n][mm] = make_float2(a1x, a1y);
            s.Apk[1][n][mm] = make_float2(a2x, a2y);
            s.Apk[2][n][mm] = make_float2(a3x, a3y);
        }
        s.b1s[o] = b1[o];
        s.b2s[o] = b2[o];
        for (int idx = o; idx < FOUT * ODIM; idx += NTHREADS)
            (&s.fcWs[0][0])[idx] = fcW[idx];
        if (o < ODIM) s.fcbs[o] = fcb[o];
        for (int idx = o; idx < NHAND * ODIM; idx += NTHREADS)
            (&s.Out[0][0])[idx] = 0.f;
    }
    __syncthreads();

    ull acc2[NHAND];
    float as[NHAND];
    ull P[11];

    // ---------------- layer 1: G1 = X @ W1 (K=256, k-packed) ----------------
    #pragma unroll
    for (int m = 0; m < NHAND; m++) acc2[m] = 0ull;
    for (int f0 = 0; f0 < FIN; f0 += 4) {
        const float* wr = W1 + f0 * DMODEL + o;
        float w0 = __ldg(wr);
        float w1 = __ldg(wr + DMODEL);
        float w2 = __ldg(wr + 2 * DMODEL);
        float w3 = __ldg(wr + 3 * DMODEL);
        ull wp01 = pack2(w0, w1), wp23 = pack2(w2, w3);
        #pragma unroll
        for (int m = 0; m < NHAND; m++) {
            ulonglong2 xv = *reinterpret_cast<const ulonglong2*>(&s.X[m][f0]);
            acc2[m] = ffma2(xv.x, wp01, acc2[m]);
            acc2[m] = ffma2(xv.y, wp23, acc2[m]);
        }
    }
    // horizontal add + repack for the mix
    #pragma unroll
    for (int m = 0; m < NHAND; m++) { float2 t = unpack2(acc2[m]); as[m] = t.x + t.y; }
    #pragma unroll
    for (int mm = 0; mm < 10; mm++) P[mm] = pack2(as[2 * mm], as[2 * mm + 1]);
    P[10] = pack2(as[20], 0.f);

    // A1-mix + bias + relu -> Buf (H1)
    {
        float bias = s.b1s[o];
        #pragma unroll
        for (int n = 0; n < NHAND; n++) {
            ull acc = 0ull;
            #pragma unroll
            for (int mm = 0; mm < 11; mm++) {
                float2 a = s.Apk[0][n][mm];
                acc = ffma2(pack2(a.x, a.y), P[mm], acc);
            }
            float2 t = unpack2(acc);
            s.Buf[n][o] = fmaxf(t.x + t.y + bias, 0.f);
        }
    }
    __syncthreads();

    // ---------------- layer 2: G2 = H1 @ W2 (K=128, k-packed) ----------------
    #pragma unroll
    for (int m = 0; m < NHAND; m++) acc2[m] = 0ull;
    for (int f0 = 0; f0 < DMODEL; f0 += 4) {
        const float* wr = W2 + f0 * DMODEL + o;
        float w0 = __ldg(wr);
        float w1 = __ldg(wr + DMODEL);
        float w2 = __ldg(wr + 2 * DMODEL);
        float w3 = __ldg(wr + 3 * DMODEL);
        ull wp01 = pack2(w0, w1), wp23 = pack2(w2, w3);
        #pragma unroll
        for (int m = 0; m < NHAND; m++) {
            ulonglong2 hv = *reinterpret_cast<const ulonglong2*>(&s.Buf[m][f0]);
            acc2[m] = ffma2(hv.x, wp01, acc2[m]);
            acc2[m] = ffma2(hv.y, wp23, acc2[m]);
        }
    }
    __syncthreads();   // done reading Buf before overwrite

    // A2-mix + bias + relu -> h2 (regs), then A3-mix -> Buf
    {
        #pragma unroll
        for (int m = 0; m < NHAND; m++) { float2 t = unpack2(acc2[m]); as[m] = t.x + t.y; }
        #pragma unroll
        for (int mm = 0; mm < 10; mm++) P[mm] = pack2(as[2 * mm], as[2 * mm + 1]);
        P[10] = pack2(as[20], 0.f);

        float h2[NHAND];
        float bias = s.b2s[o];
        #pragma unroll
        for (int n = 0; n < NHAND; n++) {
            ull acc = 0ull;
            #pragma unroll
            for (int mm = 0; mm < 11; mm++) {
                float2 a = s.Apk[1][n][mm];
                acc = ffma2(pack2(a.x, a.y), P[mm], acc);
            }
            float2 t = unpack2(acc);
            h2[n] = fmaxf(t.x + t.y + bias, 0.f);
        }
        #pragma unroll
        for (int mm = 0; mm < 10; mm++) P[mm] = pack2(h2[2 * mm], h2[2 * mm + 1]);
        P[10] = pack2(h2[20], 0.f);
        #pragma unroll
        for (int n = 0; n < NHAND; n++) {
            ull acc = 0ull;
            #pragma unroll
            for (int mm = 0; mm < 11; mm++) {
                float2 a = s.Apk[2][n][mm];
                acc = ffma2(pack2(a.x, a.y), P[mm], acc);
            }
            float2 t = unpack2(acc);
            s.Buf[n][o] = t.x + t.y;   // AH2 (pre-W3), no relu/bias here
        }
    }
    __syncthreads();

    // ---------------- layer 3: x3 = relu(AH2 @ W3 + b3), fused fc ----------------
    float bb3[4];
    #pragma unroll
    for (int c = 0; c < 4; c++) bb3[c] = __ldg(&b3[o + 128 * c]);

    for (int mc = 0; mc < NHAND; mc += 7) {     // 3 row chunks of 7
        ull a3c[7][4];
        #pragma unroll
        for (int mm = 0; mm < 7; mm++)
            #pragma unroll
            for (int c = 0; c < 4; c++) a3c[mm][c] = 0ull;

        for (int f0 = 0; f0 < DMODEL; f0 += 4) {
            ull wp[4][2];
            #pragma unroll
            for (int c = 0; c < 4; c++) {
                const float* wr = W3 + f0 * FOUT + o + 128 * c;
                float w0 = __ldg(wr);
                float w1 = __ldg(wr + FOUT);
                float w2 = __ldg(wr + 2 * FOUT);
                float w3 = __ldg(wr + 3 * FOUT);
                wp[c][0] = pack2(w0, w1);
                wp[c][1] = pack2(w2, w3);
            }
            #pragma unroll
            for (int mm = 0; mm < 7; mm++) {
                ulonglong2 hv = *reinterpret_cast<const ulonglong2*>(&s.Buf[mc + mm][f0]);
                #pragma unroll
                for (int c = 0; c < 4; c++) {
                    a3c[mm][c] = ffma2(hv.x, wp[c][0], a3c[mm][c]);
                    a3c[mm][c] = ffma2(hv.y, wp[c][1], a3c[mm][c]);
                }
            }
        }
        // relu + store x3 + fc partials
        #pragma unroll
        for (int mm = 0; mm < 7; mm++) {
            int m = mc + mm;
            float p0 = 0.f, p1 = 0.f, p2 = 0.f;
            #pragma unroll
            for (int c = 0; c < 4; c++) {
                float2 t = unpack2(a3c[mm][c]);
                float v = fmaxf(t.x + t.y + bb3[c], 0.f);
                int col = o + 128 * c;
                x3_out[((size_t)b * NHAND + m) * FOUT + col] = v;
                p0 = fmaf(v, s.fcWs[col][0], p0);
                p1 = fmaf(v, s.fcWs[col][1], p1);
                p2 = fmaf(v, s.fcWs[col][2], p2);
            }
            #pragma unroll
            for (int off = 16; off > 0; off >>= 1) {
                p0 += __shfl_down_sync(0xffffffffu, p0, off);
                p1 += __shfl_down_sync(0xffffffffu, p1, off);
                p2 += __shfl_down_sync(0xffffffffu, p2, off);
            }
            if ((o & 31) == 0) {
                atomicAdd(&s.Out[m][0], p0);
                atomicAdd(&s.Out[m][1], p1);
                atomicAdd(&s.Out[m][2], p2);
            }
        }
    }
    __syncthreads();

    // ---------------- write fc output ----------------
    if (o < NHAND * ODIM) {
        int n = o / ODIM, j = o % ODIM;
        fc_out[((size_t)b * NHAND + n) * ODIM + j] = s.Out[n][j] + s.fcbs[j];
    }
}

extern "C" void kernel_launch(void* const* d_in, const int* in_sizes, int n_in,
                              void* d_out, int out_size)
{
    const float* x   = (const float*)d_in[0];
    const float* A1  = (const float*)d_in[1];
    const float* A2  = (const float*)d_in[2];
    const float* A3  = (const float*)d_in[3];
    const float* W1  = (const float*)d_in[4];
    const float* b1  = (const float*)d_in[5];
    const float* W2  = (const float*)d_in[6];
    const float* b2  = (const float*)d_in[7];
    const float* W3  = (const float*)d_in[8];
    const float* b3  = (const float*)d_in[9];
    const float* fcW = (const float*)d_in[10];
    const float* fcb = (const float*)d_in[11];

    const int B = in_sizes[0] / (NHAND * FIN);
    float* x3_out = (float*)d_out;
    float* fc_out = x3_out + (size_t)B * NHAND * FOUT;

    handnet_fused_kernel<<<B, NTHREADS>>>(x, A1, A2, A3, W1, b1, W2, b2,
                                          W3, b3, fcW, fcb, x3_out, fc_out);
}

// round 10
// speedup vs baseline: 2.0096x; 2.0091x over previous
#include <cuda_runtime.h>
#include <cuda_bf16.h>
#include <cstddef>
#include <cstdint>

#define AH 0u
#define AL 34816u
#define WH 69632u
#define WL 104448u
#define GOF 69632u            // G buffer aliases W region
#define ASTR 272u             // act/w smem row stride bytes (128 bf16 + 16B pad)
#define GSTR 132              // G row stride floats
#define DSMEM 139264

// weight scratch planes (bf16): L1 hi@0 lo@65536 [128][256]; L2 hi@131072 lo@163840 [128][128];
// L3 hi@196608 lo@327680 [512][128]
__device__ __align__(1024) unsigned char g_wsc[458752];

__device__ __forceinline__ uint32_t su32(const void* p) {
    uint32_t a;
    asm("{ .reg .u64 t; cvta.to.shared.u64 t, %1; cvt.u32.u64 %0, t; }" : "=r"(a) : "l"(p));
    return a;
}
__device__ __forceinline__ void bsplit(float v, __nv_bfloat16& h, __nv_bfloat16& l) {
    h = __float2bfloat16(v);
    l = __float2bfloat16(v - __bfloat162float(h));
}
__device__ __forceinline__ uint32_t pk2(float a, float b) {
    __nv_bfloat16 ha, hb;
    __nv_bfloat16 la, lb;
    bsplit(a, ha, la); bsplit(b, hb, lb);
    return (uint32_t)reinterpret_cast<unsigned short&>(ha) |
           ((uint32_t)reinterpret_cast<unsigned short&>(hb) << 16);
}
__device__ __forceinline__ void pk2hl(float a, float b, uint32_t& hi, uint32_t& lo) {
    __nv_bfloat16 ha, la, hb, lb;
    bsplit(a, ha, la); bsplit(b, hb, lb);
    hi = (uint32_t)reinterpret_cast<unsigned short&>(ha) |
         ((uint32_t)reinterpret_cast<unsigned short&>(hb) << 16);
    lo = (uint32_t)reinterpret_cast<unsigned short&>(la) |
         ((uint32_t)reinterpret_cast<unsigned short&>(lb) << 16);
}
__device__ __forceinline__ void ldsm4(uint32_t a[4], uint32_t addr) {
    asm volatile("ldmatrix.sync.aligned.m8n8.x4.shared.b16 {%0,%1,%2,%3}, [%4];"
                 : "=r"(a[0]), "=r"(a[1]), "=r"(a[2]), "=r"(a[3]) : "r"(addr));
}
__device__ __forceinline__ void ldsm2(uint32_t a[2], uint32_t addr) {
    asm volatile("ldmatrix.sync.aligned.m8n8.x2.shared.b16 {%0,%1}, [%2];"
                 : "=r"(a[0]), "=r"(a[1]) : "r"(addr));
}
__device__ __forceinline__ void mmabf(float c[4], const uint32_t a[4], const uint32_t b[2]) {
    asm volatile(
        "mma.sync.aligned.m16n8k16.row.col.f32.bf16.bf16.f32 "
        "{%0,%1,%2,%3}, {%4,%5,%6,%7}, {%8,%9}, {%0,%1,%2,%3};"
        : "+f"(c[0]), "+f"(c[1]), "+f"(c[2]), "+f"(c[3])
        : "r"(a[0]), "r"(a[1]), "r"(a[2]), "r"(a[3]), "r"(b[0]), "r"(b[1]));
}

// ---------------- prep: split/transpose weights ----------------
__global__ void __launch_bounds__(256) prep_kernel(const float* __restrict__ W1,
                                                   const float* __restrict__ W2,
                                                   const float* __restrict__ W3) {
    int stride = gridDim.x * blockDim.x;
    int i0 = blockIdx.x * blockDim.x + threadIdx.x;
    __nv_bfloat16* g = (__nv_bfloat16*)g_wsc;
    for (int p = i0; p < 32768; p += stride) {           // L1 [n=128][k=256]
        int n = p >> 8, k = p & 255;
        __nv_bfloat16 h, l; bsplit(W1[(size_t)k * 128 + n], h, l);
        g[p] = h; g[32768 + p] = l;
    }
    for (int p = i0; p < 16384; p += stride) {           // L2 [128][128]
        int n = p >> 7, k = p & 127;
        __nv_bfloat16 h, l; bsplit(W2[(size_t)k * 128 + n], h, l);
        g[65536 + p] = h; g[81920 + p] = l;
    }
    for (int p = i0; p < 65536; p += stride) {           // L3 [512][128]
        int n = p >> 7, k = p & 127;
        __nv_bfloat16 h, l; bsplit(W3[(size_t)k * 512 + n], h, l);
        g[98304 + p] = h; g[163840 + p] = l;
    }
}

// copy one 128-row x 256B weight chunk (hi+lo) into padded smem tiles
__device__ __forceinline__ void copy_w(char* dyn, uint32_t hiOff, uint32_t loOff,
                                       int rowStart, int rowBytes, int colOff, int tid) {
    const char* sh = (const char*)g_wsc + hiOff + (size_t)rowStart * rowBytes + colOff;
    const char* sl = (const char*)g_wsc + loOff + (size_t)rowStart * rowBytes + colOff;
    for (int idx = tid; idx < 2048; idx += 256) {
        int n = idx >> 4, c = idx & 15;
        *(float4*)(dyn + WH + n * ASTR + c * 16) = *(const float4*)(sh + n * rowBytes + c * 16);
        *(float4*)(dyn + WL + n * ASTR + c * 16) = *(const float4*)(sl + n * rowBytes + c * 16);
    }
}

// one K=128 GEMM chunk: acc[16][4] += act(128x128 hi/lo) @ W(128n x 128k hi/lo)^T
__device__ __forceinline__ void gemm128(float acc[16][4], uint32_t sb, int wid, int lane) {
    int arow = wid * 16 + (lane & 15);
    int akoff = (lane >> 4) * 8;
    uint32_t aH0 = sb + AH + arow * ASTR + akoff * 2;
    uint32_t aL0 = sb + AL + arow * ASTR + akoff * 2;
    int bn = lane & 7;
    int bk = ((lane >> 3) & 1) * 8;
    #pragma unroll
    for (int kh = 0; kh < 2; kh++) {
        uint32_t fH[4][4], fL[4][4];
        #pragma unroll
        for (int ks = 0; ks < 4; ks++) {
            int kk = kh * 4 + ks;
            ldsm4(fH[ks], aH0 + kk * 32);
            ldsm4(fL[ks], aL0 + kk * 32);
        }
        #pragma unroll
        for (int nt = 0; nt < 16; nt++) {
            uint32_t wH0 = sb + WH + (nt * 8 + bn) * ASTR + bk * 2;
            uint32_t wL0 = sb + WL + (nt * 8 + bn) * ASTR + bk * 2;
            #pragma unroll
            for (int ks = 0; ks < 4; ks++) {
                int kk = kh * 4 + ks;
                uint32_t bH[2], bL[2];
                ldsm2(bH, wH0 + kk * 32);
                ldsm2(bL, wL0 + kk * 32);
                mmabf(acc[nt], fH[ks], bH);
                mmabf(acc[nt], fL[ks], bH);
                mmabf(acc[nt], fH[ks], bL);
            }
        }
    }
}

__global__ void __launch_bounds__(256, 1) handnet_mma(
    const float* __restrict__ x,
    const float* __restrict__ A1, const float* __restrict__ A2, const float* __restrict__ A3,
    const float* __restrict__ b1, const float* __restrict__ b2, const float* __restrict__ b3,
    const float* __restrict__ fcW, const float* __restrict__ fcb,
    float* __restrict__ x3o, float* __restrict__ fco, int R)
{
    extern __shared__ char dyn[];
    __shared__ float sA[3 * 441];
    __shared__ float sb1[128], sb2[128], sb3[512], sfw[1536], sfb[3];

    const int tid = threadIdx.x, wid = tid >> 5, lane = tid & 31;
    const int qg = lane >> 2, qt = lane & 3;
    const uint32_t sb = su32(dyn);
    const int b0row = blockIdx.x * 126;
    const int RV = min(126, R - b0row);
    float* G = (float*)(dyn + GOF);

    for (int i = tid; i < 441; i += 256) {
        sA[i] = A1[i]; sA[441 + i] = A2[i]; sA[882 + i] = A3[i];
    }
    if (tid < 128) { sb1[tid] = b1[tid]; sb2[tid] = b2[tid]; }
    for (int i = tid; i < 512; i += 256) sb3[i] = b3[i];
    for (int i = tid; i < 1536; i += 256) sfw[i] = fcW[i];
    if (tid < 3) sfb[tid] = fcb[tid];

    float acc[16][4];
    #pragma unroll
    for (int nt = 0; nt < 16; nt++)
        #pragma unroll
        for (int c = 0; c < 4; c++) acc[nt][c] = 0.f;

    // ================= layer 1: X @ W1, K=256 in 2 chunks =================
    for (int kc = 0; kc < 2; kc++) {
        __syncthreads();
        for (int idx = tid; idx < 4096; idx += 256) {       // stage X chunk -> act hi/lo
            int r = idx >> 5, c4 = idx & 31;
            float4 v = make_float4(0.f, 0.f, 0.f, 0.f);
            if (r < RV)
                v = *(const float4*)(x + (size_t)(b0row + r) * 256 + kc * 128 + c4 * 4);
            uint32_t h0, l0, h1, l1;
            pk2hl(v.x, v.y, h0, l0);
            pk2hl(v.z, v.w, h1, l1);
            uint32_t off = r * ASTR + c4 * 8;
            *(uint2*)(dyn + AH + off) = make_uint2(h0, h1);
            *(uint2*)(dyn + AL + off) = make_uint2(l0, l1);
        }
        copy_w(dyn, 0, 65536, 0, 512, kc * 256, tid);
        __syncthreads();
        gemm128(acc, sb, wid, lane);
    }

    // ---- dump G, A1-mix + b1 + relu -> act ----
    for (int layer = 0; layer < 2; layer++) {
        __syncthreads();
        {
            int r0 = wid * 16 + qg;
            #pragma unroll
            for (int nt = 0; nt < 16; nt++) {
                *(float2*)&G[r0 * GSTR + nt * 8 + 2 * qt] = make_float2(acc[nt][0], acc[nt][1]);
                *(float2*)&G[(r0 + 8) * GSTR + nt * 8 + 2 * qt] = make_float2(acc[nt][2], acc[nt][3]);
            }
        }
        __syncthreads();
        // mix: layer 0: A1+b1+relu ; layer 1: A2+b2+relu then A3
        {
            int c = tid & 127, half = tid >> 7;
            const float* Aa = (layer == 0) ? sA : sA + 441;
            const float* Ab = (layer == 0) ? nullptr : sA + 882;
            float bias = (layer == 0) ? sb1[c] : sb2[c];
            for (int pass = 0; pass < 3; pass++) {
                int e = half + 2 * pass;
                bool valid = (e * 21 < RV);
                float v[21], t1[21];
                #pragma unroll
                for (int m = 0; m < 21; m++)
                    v[m] = valid ? G[(e * 21 + m) * GSTR + c] : 0.f;
                #pragma unroll
                for (int n = 0; n < 21; n++) {
                    float h = bias;
                    #pragma unroll
                    for (int m = 0; m < 21; m++) h = fmaf(Aa[n * 21 + m], v[m], h);
                    t1[n] = fmaxf(h, 0.f);
                }
                if (Ab) {
                    #pragma unroll
                    for (int n = 0; n < 21; n++) {
                        float h = 0.f;
                        #pragma unroll
                        for (int m = 0; m < 21; m++) h = fmaf(Ab[n * 21 + m], t1[m], h);
                        v[n] = h;
                    }
                } else {
                    #pragma unroll
                    for (int n = 0; n < 21; n++) v[n] = t1[n];
                }
                #pragma unroll
                for (int n = 0; n < 21; n++) {
                    int r = e * 21 + n;
                    float val = valid ? v[n] : 0.f;
                    __nv_bfloat16 h16, l16;
                    bsplit(val, h16, l16);
                    *(__nv_bfloat16*)(dyn + AH + r * ASTR + c * 2) = h16;
                    *(__nv_bfloat16*)(dyn + AL + r * ASTR + c * 2) = l16;
                }
            }
            {   // zero pad rows 126/127
                int r = 126 + half;
                *(__nv_bfloat16*)(dyn + AH + r * ASTR + c * 2) = __float2bfloat16(0.f);
                *(__nv_bfloat16*)(dyn + AL + r * ASTR + c * 2) = __float2bfloat16(0.f);
            }
        }
        __syncthreads();
        if (layer == 0) {   // layer 2 GEMM: H1 @ W2, K=128
            copy_w(dyn, 131072, 163840, 0, 256, 0, tid);
            __syncthreads();
            #pragma unroll
            for (int nt = 0; nt < 16; nt++)
                #pragma unroll
                for (int c = 0; c < 4; c++) acc[nt][c] = 0.f;
            gemm128(acc, sb, wid, lane);
        }
    }

    // ================= layer 3: M3 @ W3 (N=512, 4 chunks) + epilogue =================
    uint32_t fH3[8][4], fL3[8][4];
    {
        int arow = wid * 16 + (lane & 15);
        int akoff = (lane >> 4) * 8;
        uint32_t aH0 = sb + AH + arow * ASTR + akoff * 2;
        uint32_t aL0 = sb + AL + arow * ASTR + akoff * 2;
        #pragma unroll
        for (int kk = 0; kk < 8; kk++) {
            ldsm4(fH3[kk], aH0 + kk * 32);
            ldsm4(fL3[kk], aL0 + kk * 32);
        }
    }
    float p[2][3];
    #pragma unroll
    for (int i = 0; i < 2; i++)
        #pragma unroll
        for (int j = 0; j < 3; j++) p[i][j] = 0.f;

    const int r0 = wid * 16 + qg, r1 = r0 + 8;
    const bool v0r = r0 < RV, v1r = r1 < RV;
    int bn = lane & 7;
    int bk = ((lane >> 3) & 1) * 8;

    for (int nc = 0; nc < 4; nc++) {
        __syncthreads();
        copy_w(dyn, 196608, 327680, nc * 128, 256, 0, tid);
        __syncthreads();
        #pragma unroll
        for (int nt = 0; nt < 16; nt++) {
            float a4[4] = {0.f, 0.f, 0.f, 0.f};
            uint32_t wH0 = sb + WH + (nt * 8 + bn) * ASTR + bk * 2;
            uint32_t wL0 = sb + WL + (nt * 8 + bn) * ASTR + bk * 2;
            #pragma unroll
            for (int kk = 0; kk < 8; kk++) {
                uint32_t bH[2], bL[2];
                ldsm2(bH, wH0 + kk * 32);
                ldsm2(bL, wL0 + kk * 32);
                mmabf(a4, fH3[kk], bH);
                mmabf(a4, fL3[kk], bH);
                mmabf(a4, fH3[kk], bL);
            }
            int col = nc * 128 + nt * 8 + 2 * qt;
            float v0 = fmaxf(a4[0] + sb3[col], 0.f);
            float v1 = fmaxf(a4[1] + sb3[col + 1], 0.f);
            float v2 = fmaxf(a4[2] + sb3[col], 0.f);
            float v3 = fmaxf(a4[3] + sb3[col + 1], 0.f);
            if (v0r) *(float2*)&x3o[(size_t)(b0row + r0) * 512 + col] = make_float2(v0, v1);
            if (v1r) *(float2*)&x3o[(size_t)(b0row + r1) * 512 + col] = make_float2(v2, v3);
            #pragma unroll
            for (int j = 0; j < 3; j++) {
                p[0][j] = fmaf(v0, sfw[col * 3 + j], p[0][j]);
                p[0][j] = fmaf(v1, sfw[(col + 1) * 3 + j], p[0][j]);
                p[1][j] = fmaf(v2, sfw[col * 3 + j], p[1][j]);
                p[1][j] = fmaf(v3, sfw[(col + 1) * 3 + j], p[1][j]);
            }
        }
    }
    // quad reduce (lanes sharing same row) and write fc output
    #pragma unroll
    for (int off = 1; off <= 2; off <<= 1)
        #pragma unroll
        for (int i = 0; i < 2; i++)
            #pragma unroll
            for (int j = 0; j < 3; j++)
                p[i][j] += __shfl_xor_sync(0xffffffffu, p[i][j], off);
    if (qt == 0) {
        if (v0r)
            #pragma unroll
            for (int j = 0; j < 3; j++)
                fco[(size_t)(b0row + r0) * 3 + j] = p[0][j] + sfb[j];
        if (v1r)
            #pragma unroll
            for (int j = 0; j < 3; j++)
                fco[(size_t)(b0row + r1) * 3 + j] = p[1][j] + sfb[j];
    }
}

extern "C" void kernel_launch(void* const* d_in, const int* in_sizes, int n_in,
                              void* d_out, int out_size)
{
    const float* x   = (const float*)d_in[0];
    const float* A1  = (const float*)d_in[1];
    const float* A2  = (const float*)d_in[2];
    const float* A3  = (const float*)d_in[3];
    const float* W1  = (const float*)d_in[4];
    const float* b1  = (const float*)d_in[5];
    const float* W2  = (const float*)d_in[6];
    const float* b2  = (const float*)d_in[7];
    const float* W3  = (const float*)d_in[8];
    const float* b3  = (const float*)d_in[9];
    const float* fcW = (const float*)d_in[10];
    const float* fcb = (const float*)d_in[11];

    const int B = in_sizes[0] / (21 * 256);
    const int R = B * 21;
    float* x3o = (float*)d_out;
    float* fco = x3o + (size_t)R * 512;

    cudaFuncSetAttribute(handnet_mma, cudaFuncAttributeMaxDynamicSharedMemorySize, DSMEM);
    prep_kernel<<<148, 256>>>(W1, W2, W3);
    handnet_mma<<<(R + 125) / 126, 256, DSMEM>>>(x, A1, A2, A3, b1, b2, b3,
                                                 fcW, fcb, x3o, fco, R);
}

// round 11
// speedup vs baseline: 2.1312x; 1.0605x over previous
#include <cuda_runtime.h>
#include <cuda_bf16.h>
#include <cstddef>
#include <cstdint>

#define ASTR 272u
#define AH0 0u
#define AL0 34816u
#define AH1 69632u
#define AL1 104448u
#define GO  139264u
#define GSTR 132
#define DSMEM 206848

// fragment-ordered bf16 weight planes, 7 (hi,lo) pairs of 32KB tiles:
// p0: W1 k0-127 @0 ; p1: W1 k128-255 @65536 ; p2: W2 @131072 ;
// p3-6: W3 n-chunk nc @196608+nc*65536   (lo plane = hi + 32768)
__device__ __align__(1024) unsigned char g_wsc[458752];

__device__ __forceinline__ uint32_t su32(const void* p) {
    uint32_t a;
    asm("{ .reg .u64 t; cvta.to.shared.u64 t, %1; cvt.u32.u64 %0, t; }" : "=r"(a) : "l"(p));
    return a;
}
__device__ __forceinline__ void bsplit(float v, __nv_bfloat16& h, __nv_bfloat16& l) {
    h = __float2bfloat16(v);
    l = __float2bfloat16(v - __bfloat162float(h));
}
__device__ __forceinline__ void pk2hl(float a, float b, uint32_t& hi, uint32_t& lo) {
    __nv_bfloat16 ha, la, hb, lb;
    bsplit(a, ha, la); bsplit(b, hb, lb);
    hi = (uint32_t)reinterpret_cast<unsigned short&>(ha) |
         ((uint32_t)reinterpret_cast<unsigned short&>(hb) << 16);
    lo = (uint32_t)reinterpret_cast<unsigned short&>(la) |
         ((uint32_t)reinterpret_cast<unsigned short&>(lb) << 16);
}
__device__ __forceinline__ void ldsm4(uint32_t a[4], uint32_t addr) {
    asm volatile("ldmatrix.sync.aligned.m8n8.x4.shared.b16 {%0,%1,%2,%3}, [%4];"
                 : "=r"(a[0]), "=r"(a[1]), "=r"(a[2]), "=r"(a[3]) : "r"(addr));
}
__device__ __forceinline__ void mmabf(float c[4], const uint32_t a[4], uint32_t b0, uint32_t b1) {
    asm volatile(
        "mma.sync.aligned.m16n8k16.row.col.f32.bf16.bf16.f32 "
        "{%0,%1,%2,%3}, {%4,%5,%6,%7}, {%8,%9}, {%0,%1,%2,%3};"
        : "+f"(c[0]), "+f"(c[1]), "+f"(c[2]), "+f"(c[3])
        : "r"(a[0]), "r"(a[1]), "r"(a[2]), "r"(a[3]), "r"(b0), "r"(b1));
}

// ---------------- prep: write weights in mma-fragment lane order ----------------
// within a 32KB tile (128n x 128k): u32 index i = (ntg<<9)|(kq<<7)|(l<<2)|r
// value = bf16x2 { W[k][n], W[k+1][n] },  k = kq*32 + (r>>1)*16 + (r&1)*8 + 2*(l&3),
//                                         n = ntg*8 + (l>>2)
__global__ void __launch_bounds__(256) prep_kernel(const float* __restrict__ W1,
                                                   const float* __restrict__ W2,
                                                   const float* __restrict__ W3) {
    int stride = gridDim.x * blockDim.x;
    for (int p = blockIdx.x * blockDim.x + threadIdx.x; p < 57344; p += stride) {
        int pair = p >> 13, i = p & 8191;
        const float* W; int N, kb, nb; uint32_t base;
        if (pair == 0)      { W = W1; N = 128; kb = 0;   nb = 0; base = 0; }
        else if (pair == 1) { W = W1; N = 128; kb = 128; nb = 0; base = 65536; }
        else if (pair == 2) { W = W2; N = 128; kb = 0;   nb = 0; base = 131072; }
        else { int nc = pair - 3; W = W3; N = 512; kb = 0; nb = nc * 128;
               base = 196608 + (uint32_t)nc * 65536; }
        int ntg = i >> 9, kq = (i >> 7) & 3, l = (i >> 2) & 31, r = i & 3;
        int kl = kq * 32 + ((r >> 1) << 4) + ((r & 1) << 3) + ((l & 3) << 1);
        int nl = ntg * 8 + (l >> 2);
        int kg = kb + kl, ng = nb + nl;
        float w0 = W[(size_t)kg * N + ng], w1 = W[(size_t)(kg + 1) * N + ng];
        uint32_t hi, lo;
        pk2hl(w0, w1, hi, lo);
        ((uint32_t*)(g_wsc + base))[i] = hi;
        ((uint32_t*)(g_wsc + base + 32768))[i] = lo;
    }
}

// one 128x128-K GEMM tile: acc[2][8][4] += act(128rows x128k, hi/lo smem) @ W^T
// warp (wm 0..3, wn 0..1): rows wm*32 + rg*16, cols wn*64 + nt*8
__device__ __forceinline__ void gemm_tile(float acc[2][8][4],
        uint32_t aHb, uint32_t aLb, const uint4* __restrict__ fH,
        const uint4* __restrict__ fL, int wm, int wn, int lane)
{
    const int arow = wm * 32 + (lane & 15);
    const int akb = (lane >> 4) * 16;
    #pragma unroll
    for (int kq = 0; kq < 4; kq++) {
        uint32_t aH[2][2][4], aL[2][2][4];
        #pragma unroll
        for (int rg = 0; rg < 2; rg++)
            #pragma unroll
            for (int s = 0; s < 2; s++) {
                uint32_t off = (uint32_t)(arow + rg * 16) * ASTR + akb + kq * 64 + s * 32;
                ldsm4(aH[rg][s], aHb + off);
                ldsm4(aL[rg][s], aLb + off);
            }
        #pragma unroll
        for (int g = 0; g < 2; g++) {
            uint4 bh[4], bl[4];
            #pragma unroll
            for (int q = 0; q < 4; q++) {
                int ntg = wn * 8 + g * 4 + q;
                bh[q] = fH[(ntg * 4 + kq) * 32 + lane];
                bl[q] = fL[(ntg * 4 + kq) * 32 + lane];
            }
            #pragma unroll
            for (int pass = 0; pass < 3; pass++)
                #pragma unroll
                for (int s = 0; s < 2; s++)
                    #pragma unroll
                    for (int q = 0; q < 4; q++) {
                        uint32_t B0, B1;
                        if (pass == 2) { B0 = s ? bl[q].z : bl[q].x; B1 = s ? bl[q].w : bl[q].y; }
                        else           { B0 = s ? bh[q].z : bh[q].x; B1 = s ? bh[q].w : bh[q].y; }
                        #pragma unroll
                        for (int rg = 0; rg < 2; rg++) {
                            const uint32_t* Af = (pass == 1) ? aL[rg][s] : aH[rg][s];
                            mmabf(acc[rg][g * 4 + q], Af, B0, B1);
                        }
                    }
        }
    }
}

__global__ void __launch_bounds__(256, 1) handnet_mma(
    const float* __restrict__ x,
    const float* __restrict__ A1, const float* __restrict__ A2, const float* __restrict__ A3,
    const float* __restrict__ b1, const float* __restrict__ b2, const float* __restrict__ b3,
    const float* __restrict__ fcW, const float* __restrict__ fcb,
    float* __restrict__ x3o, float* __restrict__ fco, int R)
{
    extern __shared__ char dyn[];
    __shared__ float sA[3 * 441];
    __shared__ float sb1[128], sb2[128], sb3[512], sfw[1536], sfb[3];
    __shared__ float OutP[128][6];

    const int tid = threadIdx.x, wid = tid >> 5, lane = tid & 31;
    const int wm = wid & 3, wn = wid >> 2;
    const uint32_t sb = su32(dyn);
    const int b0row = blockIdx.x * 126;
    const int RV = min(126, R - b0row);
    float* G = (float*)(dyn + GO);

    for (int i = tid; i < 441; i += 256) {
        sA[i] = A1[i]; sA[441 + i] = A2[i]; sA[882 + i] = A3[i];
    }
    if (tid < 128) { sb1[tid] = b1[tid]; sb2[tid] = b2[tid]; }
    for (int i = tid; i < 512; i += 256) sb3[i] = b3[i];
    for (int i = tid; i < 1536; i += 256) sfw[i] = fcW[i];
    if (tid < 3) sfb[tid] = fcb[tid];

    // ---- stage X (both K-chunks) as bf16 hi/lo, zero-padded to 128 rows ----
    for (int idx = tid; idx < 8192; idx += 256) {
        int r = idx >> 6, c4 = idx & 63;
        float4 v = make_float4(0.f, 0.f, 0.f, 0.f);
        if (r < RV) v = *(const float4*)(x + (size_t)(b0row + r) * 256 + c4 * 4);
        uint32_t h0, l0, h1, l1;
        pk2hl(v.x, v.y, h0, l0);
        pk2hl(v.z, v.w, h1, l1);
        int kc = c4 >> 5, cc = c4 & 31;
        uint32_t off = (uint32_t)r * ASTR + cc * 8;
        char* hb = dyn + (kc ? AH1 : AH0);
        char* lb = dyn + (kc ? AL1 : AL0);
        *(uint2*)(hb + off) = make_uint2(h0, h1);
        *(uint2*)(lb + off) = make_uint2(l0, l1);
    }
    __syncthreads();

    float acc[2][8][4];
    #pragma unroll
    for (int rg = 0; rg < 2; rg++)
        #pragma unroll
        for (int nt = 0; nt < 8; nt++)
            #pragma unroll
            for (int c = 0; c < 4; c++) acc[rg][nt][c] = 0.f;

    // ================= layer 1: K=256 = two fragment tiles =================
    gemm_tile(acc, sb + AH0, sb + AL0, (const uint4*)(g_wsc),
              (const uint4*)(g_wsc + 32768), wm, wn, lane);
    gemm_tile(acc, sb + AH1, sb + AL1, (const uint4*)(g_wsc + 65536),
              (const uint4*)(g_wsc + 98304), wm, wn, lane);

    for (int layer = 0; layer < 2; layer++) {
        // ---- dump acc -> G ----
        #pragma unroll
        for (int rg = 0; rg < 2; rg++) {
            int rA = wm * 32 + rg * 16 + (lane >> 2);
            #pragma unroll
            for (int nt = 0; nt < 8; nt++) {
                int col = wn * 64 + nt * 8 + 2 * (lane & 3);
                *(float2*)&G[rA * GSTR + col] = make_float2(acc[rg][nt][0], acc[rg][nt][1]);
                *(float2*)&G[(rA + 8) * GSTR + col] = make_float2(acc[rg][nt][2], acc[rg][nt][3]);
            }
        }
        __syncthreads();
        // ---- mix: layer0: A1+b1+relu ; layer1: A2+b2+relu then A3 ----
        {
            int c = tid & 127, half = tid >> 7;
            const float* Aa = (layer == 0) ? sA : sA + 441;
            const float* Ab = (layer == 0) ? nullptr : sA + 882;
            float bias = (layer == 0) ? sb1[c] : sb2[c];
            for (int pass = 0; pass < 3; pass++) {
                int e = half + 2 * pass;
                bool valid = (e * 21 < RV);
                float v[21], t1[21];
                #pragma unroll
                for (int m = 0; m < 21; m++)
                    v[m] = valid ? G[(e * 21 + m) * GSTR + c] : 0.f;
                #pragma unroll
                for (int n = 0; n < 21; n++) {
                    float h = bias;
                    #pragma unroll
                    for (int m = 0; m < 21; m++) h = fmaf(Aa[n * 21 + m], v[m], h);
                    t1[n] = fmaxf(h, 0.f);
                }
                if (Ab) {
                    #pragma unroll
                    for (int n = 0; n < 21; n++) {
                        float h = 0.f;
                        #pragma unroll
                        for (int m = 0; m < 21; m++) h = fmaf(Ab[n * 21 + m], t1[m], h);
                        v[n] = h;
                    }
                } else {
                    #pragma unroll
                    for (int n = 0; n < 21; n++) v[n] = t1[n];
                }
                #pragma unroll
                for (int n = 0; n < 21; n++) {
                    int r = e * 21 + n;
                    float val = valid ? v[n] : 0.f;
                    __nv_bfloat16 h16, l16;
                    bsplit(val, h16, l16);
                    *(__nv_bfloat16*)(dyn + AH0 + r * ASTR + c * 2) = h16;
                    *(__nv_bfloat16*)(dyn + AL0 + r * ASTR + c * 2) = l16;
                }
            }
            {   // keep pad rows zero
                int r = 126 + half;
                *(__nv_bfloat16*)(dyn + AH0 + r * ASTR + c * 2) = __float2bfloat16(0.f);
                *(__nv_bfloat16*)(dyn + AL0 + r * ASTR + c * 2) = __float2bfloat16(0.f);
            }
        }
        __syncthreads();
        if (layer == 0) {   // layer 2 GEMM
            #pragma unroll
            for (int rg = 0; rg < 2; rg++)
                #pragma unroll
                for (int nt = 0; nt < 8; nt++)
                    #pragma unroll
                    for (int c = 0; c < 4; c++) acc[rg][nt][c] = 0.f;
            gemm_tile(acc, sb + AH0, sb + AL0, (const uint4*)(g_wsc + 131072),
                      (const uint4*)(g_wsc + 163840), wm, wn, lane);
        }
    }

    // ================= layer 3: N=512 in 4 chunks + fused epilogue =================
    float p[4][3];
    #pragma unroll
    for (int i = 0; i < 4; i++)
        #pragma unroll
        for (int j = 0; j < 3; j++) p[i][j] = 0.f;

    for (int nc = 0; nc < 4; nc++) {
        #pragma unroll
        for (int rg = 0; rg < 2; rg++)
            #pragma unroll
            for (int nt = 0; nt < 8; nt++)
                #pragma unroll
                for (int c = 0; c < 4; c++) acc[rg][nt][c] = 0.f;
        gemm_tile(acc, sb + AH0, sb + AL0,
                  (const uint4*)(g_wsc + 196608 + (uint32_t)nc * 65536),
                  (const uint4*)(g_wsc + 196608 + (uint32_t)nc * 65536 + 32768),
                  wm, wn, lane);
        int colb = nc * 128 + wn * 64;
        #pragma unroll
        for (int rg = 0; rg < 2; rg++) {
            int rA = wm * 32 + rg * 16 + (lane >> 2), rB = rA + 8;
            bool vA = rA < RV, vB = rB < RV;
            #pragma unroll
            for (int nt = 0; nt < 8; nt++) {
                int col = colb + nt * 8 + 2 * (lane & 3);
                float v0 = fmaxf(acc[rg][nt][0] + sb3[col], 0.f);
                float v1 = fmaxf(acc[rg][nt][1] + sb3[col + 1], 0.f);
                float v2 = fmaxf(acc[rg][nt][2] + sb3[col], 0.f);
                float v3 = fmaxf(acc[rg][nt][3] + sb3[col + 1], 0.f);
                if (vA) *(float2*)&x3o[(size_t)(b0row + rA) * 512 + col] = make_float2(v0, v1);
                if (vB) *(float2*)&x3o[(size_t)(b0row + rB) * 512 + col] = make_float2(v2, v3);
                #pragma unroll
                for (int j = 0; j < 3; j++) {
                    p[rg * 2 + 0][j] = fmaf(v0, sfw[col * 3 + j],
                                        fmaf(v1, sfw[(col + 1) * 3 + j], p[rg * 2 + 0][j]));
                    p[rg * 2 + 1][j] = fmaf(v2, sfw[col * 3 + j],
                                        fmaf(v3, sfw[(col + 1) * 3 + j], p[rg * 2 + 1][j]));
                }
            }
        }
    }
    // quad reduce over lanes sharing the same row, then combine wn halves via smem
    #pragma unroll
    for (int off = 1; off <= 2; off <<= 1)
        #pragma unroll
        for (int i = 0; i < 4; i++)
            #pragma unroll
            for (int j = 0; j < 3; j++)
                p[i][j] += __shfl_xor_sync(0xffffffffu, p[i][j], off);
    if ((lane & 3) == 0) {
        #pragma unroll
        for (int rg = 0; rg < 2; rg++) {
            int rA = wm * 32 + rg * 16 + (lane >> 2);
            #pragma unroll
            for (int j = 0; j < 3; j++) {
                OutP[rA][wn * 3 + j] = p[rg * 2 + 0][j];
                OutP[rA + 8][wn * 3 + j] = p[rg * 2 + 1][j];
            }
        }
    }
    __syncthreads();
    for (int t2 = tid; t2 < 378; t2 += 256) {
        int r = t2 / 3, j = t2 % 3;
        if (r < RV)
            fco[(size_t)(b0row + r) * 3 + j] = OutP[r][j] + OutP[r][3 + j] + sfb[j];
    }
}

extern "C" void kernel_launch(void* const* d_in, const int* in_sizes, int n_in,
                              void* d_out, int out_size)
{
    const float* x   = (const float*)d_in[0];
    const float* A1  = (const float*)d_in[1];
    const float* A2  = (const float*)d_in[2];
    const float* A3  = (const float*)d_in[3];
    const float* W1  = (const float*)d_in[4];
    const float* b1  = (const float*)d_in[5];
    const float* W2  = (const float*)d_in[6];
    const float* b2  = (const float*)d_in[7];
    const float* W3  = (const float*)d_in[8];
    const float* b3  = (const float*)d_in[9];
    const float* fcW = (const float*)d_in[10];
    const float* fcb = (const float*)d_in[11];

    const int B = in_sizes[0] / (21 * 256);
    const int R = B * 21;
    float* x3o = (float*)d_out;
    float* fco = x3o + (size_t)R * 512;

    cudaFuncSetAttribute(handnet_mma, cudaFuncAttributeMaxDynamicSharedMemorySize, DSMEM);
    prep_kernel<<<112, 256>>>(W1, W2, W3);
    handnet_mma<<<(R + 125) / 126, 256, DSMEM>>>(x, A1, A2, A3, b1, b2, b3,
                                                 fcW, fcb, x3o, fco, R);
}